// round 12
// baseline (speedup 1.0000x reference)
#include <cuda_runtime.h>
#include <cuda_bf16.h>
#include <math.h>
#include <stdint.h>

// ================= scratch (device globals: allocation-free) =================
__device__ float g_Kt [64u*128u*960u];   // Kt, then reused as KVtT [64][960][128]
__device__ float g_KVt[64u*128u*960u];   // KVt [64][128][960]
__device__ float g_QtT[64u*960u*128u];   // QtT concat: [64][mrow 960][128]
__device__ float g_S  [64u*960u*960u];   // S concat:  [64][mrow 960][960]
__device__ float g_O  [8192u*960u];      // O concat:  [8192 tokens][ch 960]
__device__ float g_part[65536];          // per-(group,block) (sum,ss)
__device__ float g_stats[512];           // (mean,rstd) per group (256 groups)

// ================= per-branch GEMM params =================
struct GP {
    const float* A[4]; const float* B[4]; float* C[4];
    int  K[4], lda[4], ldb[4], ldc[4], aMask[4], bMask[4];
    long aS[4], bS[4], cS[4];
    float alpha[4];
    int cum0, cum1, cum2;      // cumulative tile thresholds for branch lookup
};

// ================= helpers =================
__device__ __forceinline__ void mma_bf16(float* c, const uint32_t* a, const uint32_t* b)
{
    asm volatile(
        "mma.sync.aligned.m16n8k16.row.col.f32.bf16.bf16.f32 "
        "{%0,%1,%2,%3}, {%4,%5,%6,%7}, {%8,%9}, {%0,%1,%2,%3};"
        : "+f"(c[0]), "+f"(c[1]), "+f"(c[2]), "+f"(c[3])
        : "r"(a[0]), "r"(a[1]), "r"(a[2]), "r"(a[3]), "r"(b[0]), "r"(b[1]));
}

__device__ __forceinline__ void ldsm_x4(uint32_t* r, uint32_t addr)
{
    asm volatile("ldmatrix.sync.aligned.m8n8.x4.shared.b16 {%0,%1,%2,%3}, [%4];"
        : "=r"(r[0]), "=r"(r[1]), "=r"(r[2]), "=r"(r[3]) : "r"(addr));
}

__device__ __forceinline__ void ldsm_x2(uint32_t* r, uint32_t addr)
{
    asm volatile("ldmatrix.sync.aligned.m8n8.x2.shared.b16 {%0,%1}, [%2];"
        : "=r"(r[0]), "=r"(r[1]) : "r"(addr));
}

__device__ __forceinline__ void split2(float x, float y, __nv_bfloat162& h, __nv_bfloat162& l)
{
    h.x = __float2bfloat16(x); h.y = __float2bfloat16(y);
    l.x = __float2bfloat16(x - __bfloat162float(h.x));
    l.y = __float2bfloat16(y - __bfloat162float(h.y));
}

// ================= merged NT GEMM, fp32 in/out, hi/lo split MMA, ldmatrix ====
// C[m,n] = alpha * sum_k A[m,k]*B[n,k].  BM=BN=64, BK=32, 128 threads.
// AXIS 0: branch from blockIdx.y (M merged).  AXIS 1: branch from blockIdx.x (N merged).
// MODE 0: plain.  MODE 2: also emit per-block (sum,sumsq) partials for stats.
template<int AXIS, int MODE>
__global__ void __launch_bounds__(128)
gemm_mg(GP gp, float* __restrict__ part)
{
    constexpr int LDT = 40;                            // 80B row stride (16B-aligned, bank-spread)
    __shared__ __nv_bfloat16 Ah[64][LDT], Al[64][LDT], Bh[64][LDT], Bl[64][LDT];

    const int t = (AXIS == 0) ? blockIdx.y : blockIdx.x;
    int br, tl;
    if      (t < gp.cum0) { br = 0; tl = t; }
    else if (t < gp.cum1) { br = 1; tl = t - gp.cum0; }
    else if (t < gp.cum2) { br = 2; tl = t - gp.cum1; }
    else                  { br = 3; tl = t - gp.cum2; }

    const float *A, *B; float* C;
    int K, lda, ldb, ldc, aM, bM; long aS, bS, cS; float alpha;
#define PICK(i) { A=gp.A[i]; B=gp.B[i]; C=gp.C[i]; K=gp.K[i]; lda=gp.lda[i]; ldb=gp.ldb[i]; \
                  ldc=gp.ldc[i]; aM=gp.aMask[i]; bM=gp.bMask[i]; aS=gp.aS[i]; bS=gp.bS[i]; \
                  cS=gp.cS[i]; alpha=gp.alpha[i]; }
    switch (br) { case 0: PICK(0); break; case 1: PICK(1); break;
                  case 2: PICK(2); break; default: PICK(3); break; }
#undef PICK

    const int z = blockIdx.z;
    A += (long)(z & aM) * aS;
    B += (long)(z & bM) * bS;
    C += (long)z * cS;

    const int m0 = (AXIS == 0 ? tl : (int)blockIdx.y) * 64;
    const int n0 = (AXIS == 0 ? (int)blockIdx.x : tl) * 64;
    const int tid = threadIdx.x, lane = tid & 31, warp = tid >> 5;
    const int wy = warp >> 1, wx = warp & 1;       // 2x2 warps, each 32x32
    const int m0w = wy * 32, n0w = wx * 32;
    const int r = lane >> 2, p = lane & 3;

    // ---- per-thread ldmatrix base addresses (computed once) ----
    const uint32_t baseAh = (uint32_t)__cvta_generic_to_shared(&Ah[0][0]);
    const uint32_t baseAl = (uint32_t)__cvta_generic_to_shared(&Al[0][0]);
    const uint32_t baseBh = (uint32_t)__cvta_generic_to_shared(&Bh[0][0]);
    const uint32_t baseBl = (uint32_t)__cvta_generic_to_shared(&Bl[0][0]);
    // A x4: row = m0w + (lane&15) [+ mt*16], col = (lane>=16 ? 8 : 0) [+ ks]
    const uint32_t aOff = (uint32_t)((m0w + (lane & 15)) * LDT + ((lane >= 16) ? 8 : 0)) * 2;
    // B x2: row = n0w + (lane&7) [+ nt*8], col = ((lane&8) ? 8 : 0) [+ ks]   (lanes 0-15)
    const uint32_t bOff = (uint32_t)((n0w + (lane & 7)) * LDT + ((lane & 8) ? 8 : 0)) * 2;

    float acc[2][4][4];
#pragma unroll
    for (int mt = 0; mt < 2; mt++)
#pragma unroll
        for (int nt = 0; nt < 4; nt++)
#pragma unroll
            for (int i = 0; i < 4; i++) acc[mt][nt][i] = 0.f;

    for (int k0 = 0; k0 < K; k0 += 32) {
        // ---- stage A (64x32 fp32 -> hi/lo bf16) ----
#pragma unroll
        for (int it = 0; it < 4; it++) {
            int idx = tid + it * 128;
            int kq = idx & 7, m = idx >> 3;
            float4 v = *reinterpret_cast<const float4*>(&A[(long)(m0 + m) * lda + k0 + kq * 4]);
            __nv_bfloat162 h0, l0, h1, l1;
            split2(v.x, v.y, h0, l0);
            split2(v.z, v.w, h1, l1);
            *reinterpret_cast<__nv_bfloat162*>(&Ah[m][kq * 4])     = h0;
            *reinterpret_cast<__nv_bfloat162*>(&Ah[m][kq * 4 + 2]) = h1;
            *reinterpret_cast<__nv_bfloat162*>(&Al[m][kq * 4])     = l0;
            *reinterpret_cast<__nv_bfloat162*>(&Al[m][kq * 4 + 2]) = l1;
        }
#pragma unroll
        for (int it = 0; it < 4; it++) {
            int idx = tid + it * 128;
            int kq = idx & 7, n = idx >> 3;
            float4 v = *reinterpret_cast<const float4*>(&B[(long)(n0 + n) * ldb + k0 + kq * 4]);
            __nv_bfloat162 h0, l0, h1, l1;
            split2(v.x, v.y, h0, l0);
            split2(v.z, v.w, h1, l1);
            *reinterpret_cast<__nv_bfloat162*>(&Bh[n][kq * 4])     = h0;
            *reinterpret_cast<__nv_bfloat162*>(&Bh[n][kq * 4 + 2]) = h1;
            *reinterpret_cast<__nv_bfloat162*>(&Bl[n][kq * 4])     = l0;
            *reinterpret_cast<__nv_bfloat162*>(&Bl[n][kq * 4 + 2]) = l1;
        }
        __syncthreads();

#pragma unroll
        for (int ks = 0; ks < 32; ks += 16) {
            const uint32_t kbyte = (uint32_t)ks * 2;
            uint32_t ah[2][4], al[2][4], bh[4][2], bl[4][2];
#pragma unroll
            for (int mt = 0; mt < 2; mt++) {
                ldsm_x4(ah[mt], baseAh + aOff + (uint32_t)(mt * 16 * LDT) * 2 + kbyte);
                ldsm_x4(al[mt], baseAl + aOff + (uint32_t)(mt * 16 * LDT) * 2 + kbyte);
            }
#pragma unroll
            for (int nt = 0; nt < 4; nt++) {
                ldsm_x2(bh[nt], baseBh + bOff + (uint32_t)(nt * 8 * LDT) * 2 + kbyte);
                ldsm_x2(bl[nt], baseBl + bOff + (uint32_t)(nt * 8 * LDT) * 2 + kbyte);
            }
#pragma unroll
            for (int mt = 0; mt < 2; mt++)
#pragma unroll
                for (int nt = 0; nt < 4; nt++) {
                    mma_bf16(acc[mt][nt], ah[mt], bh[nt]);  // hi*hi
                    mma_bf16(acc[mt][nt], ah[mt], bl[nt]);  // hi*lo
                    mma_bf16(acc[mt][nt], al[mt], bh[nt]);  // lo*hi
                }
        }
        __syncthreads();
    }

    // ---- epilogue ----
    float sum = 0.f, ss = 0.f;
#pragma unroll
    for (int mt = 0; mt < 2; mt++) {
        int row = m0 + m0w + mt * 16 + r;
#pragma unroll
        for (int nt = 0; nt < 4; nt++) {
            int col = n0 + n0w + nt * 8 + 2 * p;
            float x0 = alpha * acc[mt][nt][0], y0 = alpha * acc[mt][nt][1];
            float x1 = alpha * acc[mt][nt][2], y1 = alpha * acc[mt][nt][3];
            *reinterpret_cast<float2*>(&C[(long)row * ldc + col])       = make_float2(x0, y0);
            *reinterpret_cast<float2*>(&C[(long)(row + 8) * ldc + col]) = make_float2(x1, y1);
            if (MODE == 2) {
                sum += x0 + y0 + x1 + y1;
                ss  += x0*x0 + y0*y0 + x1*x1 + y1*y1;
            }
        }
    }
    if (MODE == 2) {
#pragma unroll
        for (int o = 16; o; o >>= 1) {
            sum += __shfl_xor_sync(0xffffffffu, sum, o);
            ss  += __shfl_xor_sync(0xffffffffu, ss, o);
        }
        __shared__ float red[8];
        if (lane == 0) { red[warp] = sum; red[4 + warp] = ss; }
        __syncthreads();
        if (tid == 0) {
            float s1 = red[0] + red[1] + red[2] + red[3];
            float s2 = red[4] + red[5] + red[6] + red[7];
            int g  = br * 64 + z;                       // group = (branch, bh)
            int bz = tl * gridDim.x + blockIdx.x;       // local block id within group (<120)
            part[((long)g * 128 + bz) * 2 + 0] = s1;
            part[((long)g * 128 + bz) * 2 + 1] = s2;
        }
    }
}

// ================= stats finalize: 256 groups, deterministic =================
__global__ void stats_fin(const float* __restrict__ part, float* __restrict__ stats)
{
    const int g = blockIdx.x;          // 0..255
    const int br = g >> 6;
    const int nbTab[4]  = {15, 30, 60, 120};
    const float ivTab[4] = {1.f/(64*960.f), 1.f/(128*960.f), 1.f/(256*960.f), 1.f/(512*960.f)};
    const int nb = nbTab[br];
    const int tid = threadIdx.x;
    __shared__ float s1[128], s2[128];
    float a = 0.f, b = 0.f;
    for (int i = tid; i < nb; i += 128) {
        a += part[((long)g * 128 + i) * 2 + 0];
        b += part[((long)g * 128 + i) * 2 + 1];
    }
    s1[tid] = a; s2[tid] = b; __syncthreads();
    for (int o = 64; o; o >>= 1) {
        if (tid < o) { s1[tid] += s1[tid + o]; s2[tid] += s2[tid + o]; }
        __syncthreads();
    }
    if (tid == 0) {
        float m = s1[0] * ivTab[br];
        float v = s2[0] * ivTab[br] - m * m;
        stats[2 * g]     = m;
        stats[2 * g + 1] = rsqrtf(v + 1e-5f);
    }
}

// ================= warp-per-row inorm apply + softmax over 960 (in place) ====
__global__ void inorm_softmax_warp(float* __restrict__ S, const float* __restrict__ stats)
{
    const int warp = threadIdx.x >> 5, lane = threadIdx.x & 31;
    const int row = blockIdx.x * 8 + warp;           // 61440 rows total
    const int z = row / 960, mr = row - z * 960;
    const int br = (mr < 64) ? 0 : (mr < 192) ? 1 : (mr < 448) ? 2 : 3;
    const int g = br * 64 + z;
    float* p = S + (long)row * 960;
    const float mean = stats[2 * g], rstd = stats[2 * g + 1];

    // 240 float4 per row over 32 lanes: 7 full rounds + half round (lanes 0-15)
    float4 v[8];
    float mx = -1e30f;
#pragma unroll
    for (int i = 0; i < 7; i++) {
        float4 t = *reinterpret_cast<float4*>(&p[(lane + 32 * i) * 4]);
        t.x = (t.x - mean) * rstd; t.y = (t.y - mean) * rstd;
        t.z = (t.z - mean) * rstd; t.w = (t.w - mean) * rstd;
        v[i] = t;
        mx = fmaxf(mx, fmaxf(fmaxf(t.x, t.y), fmaxf(t.z, t.w)));
    }
    if (lane < 16) {
        float4 t = *reinterpret_cast<float4*>(&p[(224 + lane) * 4]);
        t.x = (t.x - mean) * rstd; t.y = (t.y - mean) * rstd;
        t.z = (t.z - mean) * rstd; t.w = (t.w - mean) * rstd;
        v[7] = t;
        mx = fmaxf(mx, fmaxf(fmaxf(t.x, t.y), fmaxf(t.z, t.w)));
    }
#pragma unroll
    for (int o = 16; o; o >>= 1) mx = fmaxf(mx, __shfl_xor_sync(0xffffffffu, mx, o));

    float sum = 0.f;
#pragma unroll
    for (int i = 0; i < 7; i++) {
        v[i].x = __expf(v[i].x - mx); v[i].y = __expf(v[i].y - mx);
        v[i].z = __expf(v[i].z - mx); v[i].w = __expf(v[i].w - mx);
        sum += v[i].x + v[i].y + v[i].z + v[i].w;
    }
    if (lane < 16) {
        v[7].x = __expf(v[7].x - mx); v[7].y = __expf(v[7].y - mx);
        v[7].z = __expf(v[7].z - mx); v[7].w = __expf(v[7].w - mx);
        sum += v[7].x + v[7].y + v[7].z + v[7].w;
    }
#pragma unroll
    for (int o = 16; o; o >>= 1) sum += __shfl_xor_sync(0xffffffffu, sum, o);
    const float inv = 1.f / sum;

#pragma unroll
    for (int i = 0; i < 7; i++) {
        v[i].x *= inv; v[i].y *= inv; v[i].z *= inv; v[i].w *= inv;
        *reinterpret_cast<float4*>(&p[(lane + 32 * i) * 4]) = v[i];
    }
    if (lane < 16) {
        v[7].x *= inv; v[7].y *= inv; v[7].z *= inv; v[7].w *= inv;
        *reinterpret_cast<float4*>(&p[(224 + lane) * 4]) = v[7];
    }
}

// ================= transpose: [z][128][960] -> [z][960][128], fp32 ===========
__global__ void transpose_kvt(const float* __restrict__ in, float* __restrict__ out)
{
    __shared__ float t[32][33];
    const int b = blockIdx.z;
    const int s0 = blockIdx.x * 32, n0 = blockIdx.y * 32;
    in  += (long)b * 128 * 960;
    out += (long)b * 960 * 128;
    const int tx = threadIdx.x, ty = threadIdx.y;
#pragma unroll
    for (int i = 0; i < 4; i++)
        t[ty + 8 * i][tx] = in[(long)(n0 + ty + 8 * i) * 960 + s0 + tx];
    __syncthreads();
#pragma unroll
    for (int i = 0; i < 4; i++)
        out[(long)(s0 + ty + 8 * i) * 128 + n0 + tx] = t[tx][ty + 8 * i];
}

// ================= host side =================
extern "C" void kernel_launch(void* const* d_in, const int* in_sizes, int n_in,
                              void* d_out, int out_size)
{
    const float* Q[4]  = {(const float*)d_in[0], (const float*)d_in[1],
                          (const float*)d_in[2], (const float*)d_in[3]};
    const float* KV    = (const float*)d_in[4];
    const float* Wk    = (const float*)d_in[5];
    const float* Wv    = (const float*)d_in[6];
    const float* Wq[4] = {(const float*)d_in[7], (const float*)d_in[8],
                          (const float*)d_in[9], (const float*)d_in[10]};
    const float* Wo[4] = {(const float*)d_in[11], (const float*)d_in[12],
                          (const float*)d_in[13], (const float*)d_in[14]};
    float* out = (float*)d_out;

    float *Kt, *KVt, *QtT, *S, *O, *part, *stats;
    cudaGetSymbolAddress((void**)&Kt,   g_Kt);
    cudaGetSymbolAddress((void**)&KVt,  g_KVt);
    cudaGetSymbolAddress((void**)&QtT,  g_QtT);
    cudaGetSymbolAddress((void**)&S,    g_S);
    cudaGetSymbolAddress((void**)&O,    g_O);
    cudaGetSymbolAddress((void**)&part, g_part);
    cudaGetSymbolAddress((void**)&stats,g_stats);

    const int FULL = 0x7FFFFFFF;
    const float inv_scale = 1.0f / sqrtf(960.0f);
    const int Cq[4]   = {64, 128, 256, 512};
    const int moff[4] = {0, 64, 192, 448};   // concat row offsets (sum = 960)

    GP gp;

    // ---- 1) Kt = KV @ Wk^T ----
    for (int i = 0; i < 4; i++) {
        gp.A[i] = KV;  gp.B[i] = Wk;  gp.C[i] = Kt;
        gp.K[i] = 960; gp.lda[i] = 960; gp.ldb[i] = 960; gp.ldc[i] = 960;
        gp.aMask[i] = FULL; gp.bMask[i] = 7;
        gp.aS[i] = 128L*960; gp.bS[i] = 960L*960; gp.cS[i] = 128L*960;
        gp.alpha[i] = 1.f;
    }
    gp.cum0 = 1000; gp.cum1 = 1001; gp.cum2 = 1002;
    gemm_mg<0,0><<<dim3(15, 2, 64), 128>>>(gp, part);

    // ---- 2) KVt = Kt @ Wv^T ----
    for (int i = 0; i < 4; i++) { gp.A[i] = Kt; gp.B[i] = Wv; gp.C[i] = KVt; }
    gemm_mg<0,0><<<dim3(15, 2, 64), 128>>>(gp, part);

    // ---- 3) KVtT [z][960][128] (reuse Kt) ----
    float* KVtT = Kt;
    transpose_kvt<<<dim3(30, 4, 64), dim3(32, 8)>>>(KVt, KVtT);

    // ---- 4) QtT merged: QtT[c,n] = sum_k Wq[c,k] * Q[n,k]  (M=Cq merged on y) ----
    for (int i = 0; i < 4; i++) {
        gp.A[i] = Wq[i];          gp.B[i] = Q[i];           gp.C[i] = QtT + (long)moff[i] * 128;
        gp.K[i] = Cq[i];          gp.lda[i] = Cq[i];        gp.ldb[i] = Cq[i];  gp.ldc[i] = 128;
        gp.aMask[i] = 7;          gp.bMask[i] = FULL;
        gp.aS[i] = (long)Cq[i]*Cq[i]; gp.bS[i] = 128L*Cq[i]; gp.cS[i] = 960L*128;
        gp.alpha[i] = 1.f;
    }
    gp.cum0 = 1; gp.cum1 = 3; gp.cum2 = 7;   // m-tiles {1,2,4,8}
    gemm_mg<0,0><<<dim3(2, 15, 64), 128>>>(gp, part);

    // ---- 5) S merged: S[c,s] = inv_scale * sum_n QtT[c,n]*KVtT[s,n]  (+ stats partials) ----
    for (int i = 0; i < 4; i++) {
        gp.A[i] = QtT + (long)moff[i] * 128;  gp.B[i] = KVtT;  gp.C[i] = S + (long)moff[i] * 960;
        gp.K[i] = 128;  gp.lda[i] = 128; gp.ldb[i] = 128; gp.ldc[i] = 960;
        gp.aMask[i] = FULL; gp.bMask[i] = FULL;
        gp.aS[i] = 960L*128; gp.bS[i] = 960L*128; gp.cS[i] = 960L*960;
        gp.alpha[i] = inv_scale;
    }
    gp.cum0 = 1; gp.cum1 = 3; gp.cum2 = 7;
    gemm_mg<0,2><<<dim3(15, 15, 64), 128>>>(gp, part);

    // ---- 6) stats + 7) softmax (warp-per-row, in place) ----
    stats_fin<<<256, 128>>>(part, stats);
    inorm_softmax_warp<<<7680, 256>>>(S, stats);

    // ---- 8) O merged: O[n,c] = sum_s KVt[n,s]*P[c,s]  (N=Cq merged on x) ----
    for (int i = 0; i < 4; i++) {
        gp.A[i] = KVt;  gp.B[i] = S + (long)moff[i] * 960;  gp.C[i] = O + moff[i];
        gp.K[i] = 960;  gp.lda[i] = 960; gp.ldb[i] = 960;   gp.ldc[i] = 960;
        gp.aMask[i] = FULL; gp.bMask[i] = FULL;
        gp.aS[i] = 128L*960; gp.bS[i] = 960L*960; gp.cS[i] = 128L*960;
        gp.alpha[i] = 1.f;
    }
    gp.cum0 = 1; gp.cum1 = 3; gp.cum2 = 7;   // n-tiles {1,2,4,8}
    gemm_mg<1,0><<<dim3(15, 2, 64), 128>>>(gp, part);

    // ---- 9) Wo merged: Y = O @ Wo^T  (N=Cq merged on x, M=8192) ----
    for (int i = 0; i < 4; i++) {
        gp.A[i] = O + moff[i];  gp.B[i] = Wo[i];  gp.C[i] = out + 8192L * moff[i];
        gp.K[i] = Cq[i];  gp.lda[i] = 960; gp.ldb[i] = Cq[i]; gp.ldc[i] = Cq[i];
        gp.aMask[i] = 0; gp.bMask[i] = 0;
        gp.aS[i] = 0; gp.bS[i] = 0; gp.cS[i] = 0;
        gp.alpha[i] = 1.f;
    }
    gp.cum0 = 1; gp.cum1 = 3; gp.cum2 = 7;
    gemm_mg<1,0><<<dim3(15, 128, 1), 128>>>(gp, part);
}

// round 13
// speedup vs baseline: 1.2999x; 1.2999x over previous
#include <cuda_runtime.h>
#include <cuda_bf16.h>
#include <math.h>
#include <stdint.h>

// ================= scratch (device globals: allocation-free) =================
__device__ float g_Kt [64u*128u*960u];   // Kt, then reused as KVtT [64][960][128]
__device__ float g_KVt[64u*128u*960u];   // KVt [64][128][960]
__device__ float g_QtT[64u*960u*128u];   // QtT concat: [64][mrow 960][128]
__device__ float g_S  [64u*960u*960u];   // S concat:  [64][mrow 960][960]
__device__ __nv_bfloat16 g_P[58982400];  // P concat:  [64][mrow 960][960] bf16
__device__ float g_O  [8192u*960u];      // O concat:  [8192 tokens][ch 960]
__device__ float g_part[65536];          // per-(group,block) (sum,ss)
__device__ float g_stats[512];           // (mean,rstd) per group (256 groups)

// ================= per-branch GEMM params =================
struct GP {
    const float* A[4]; const float* B[4]; float* C[4];
    int  K[4], lda[4], ldb[4], ldc[4], aMask[4], bMask[4];
    long aS[4], bS[4], cS[4];
    float alpha[4];
    int cum0, cum1, cum2;      // cumulative tile thresholds for branch lookup
};

// ================= helpers =================
__device__ __forceinline__ void mma_bf16(float* c, const uint32_t* a, const uint32_t* b)
{
    asm volatile(
        "mma.sync.aligned.m16n8k16.row.col.f32.bf16.bf16.f32 "
        "{%0,%1,%2,%3}, {%4,%5,%6,%7}, {%8,%9}, {%0,%1,%2,%3};"
        : "+f"(c[0]), "+f"(c[1]), "+f"(c[2]), "+f"(c[3])
        : "r"(a[0]), "r"(a[1]), "r"(a[2]), "r"(a[3]), "r"(b[0]), "r"(b[1]));
}

__device__ __forceinline__ void split2u(float x, float y, uint32_t& h, uint32_t& l)
{
    __nv_bfloat162 hh, ll;
    hh.x = __float2bfloat16(x); hh.y = __float2bfloat16(y);
    ll.x = __float2bfloat16(x - __bfloat162float(hh.x));
    ll.y = __float2bfloat16(y - __bfloat162float(hh.y));
    h = *reinterpret_cast<uint32_t*>(&hh);
    l = *reinterpret_cast<uint32_t*>(&ll);
}

// ================= merged NT GEMM, fp32 out, hi/lo-interleaved smem ==========
// C[m,n] = alpha * sum_k A[m,k]*B[n,k].  BM=BN=64, BK=32, 128 threads.
// smem element = uint2 {hi bf16-pair, lo bf16-pair}; row stride 20 elems (160B).
// AXIS 0: branch from blockIdx.y (M merged).  AXIS 1: branch from blockIdx.x.
// MODE 0: plain. MODE 2: + per-block (sum,sumsq) partials.
// BSP 1: B is fp32 (split, 3 products). BSP 0: B is bf16 (2 products).
template<int AXIS, int MODE, int BSP>
__global__ void __launch_bounds__(128)
gemm_mg(GP gp, float* __restrict__ part)
{
    constexpr int LDE = 20;                       // uint2 elems per row (160B stride)
    __shared__ uint2 sA[64][LDE];
    __shared__ uint2 sB[64][LDE];

    const int t = (AXIS == 0) ? blockIdx.y : blockIdx.x;
    int br, tl;
    if      (t < gp.cum0) { br = 0; tl = t; }
    else if (t < gp.cum1) { br = 1; tl = t - gp.cum0; }
    else if (t < gp.cum2) { br = 2; tl = t - gp.cum1; }
    else                  { br = 3; tl = t - gp.cum2; }

    const float *A, *B; float* C;
    int K, lda, ldb, ldc, aM, bM; long aS, bS, cS; float alpha;
#define PICK(i) { A=gp.A[i]; B=gp.B[i]; C=gp.C[i]; K=gp.K[i]; lda=gp.lda[i]; ldb=gp.ldb[i]; \
                  ldc=gp.ldc[i]; aM=gp.aMask[i]; bM=gp.bMask[i]; aS=gp.aS[i]; bS=gp.bS[i]; \
                  cS=gp.cS[i]; alpha=gp.alpha[i]; }
    switch (br) { case 0: PICK(0); break; case 1: PICK(1); break;
                  case 2: PICK(2); break; default: PICK(3); break; }
#undef PICK

    const int z = blockIdx.z;
    A += (long)(z & aM) * aS;
    const __nv_bfloat16* Bb = nullptr;
    if (BSP == 1) B += (long)(z & bM) * bS;
    else          Bb = reinterpret_cast<const __nv_bfloat16*>(B) + (long)(z & bM) * bS;
    C += (long)z * cS;

    const int m0 = (AXIS == 0 ? tl : (int)blockIdx.y) * 64;
    const int n0 = (AXIS == 0 ? (int)blockIdx.x : tl) * 64;
    const int tid = threadIdx.x, lane = tid & 31, warp = tid >> 5;
    const int wy = warp >> 1, wx = warp & 1;       // 2x2 warps, each 32x32
    const int m0w = wy * 32, n0w = wx * 32;
    const int r = lane >> 2, p = lane & 3;

    float acc[2][4][4];
#pragma unroll
    for (int mt = 0; mt < 2; mt++)
#pragma unroll
        for (int nt = 0; nt < 4; nt++)
#pragma unroll
            for (int i = 0; i < 4; i++) acc[mt][nt][i] = 0.f;

    for (int k0 = 0; k0 < K; k0 += 32) {
        // ---- stage A (64x32 fp32 -> interleaved hi/lo), 1 STS.128 per float4 ----
#pragma unroll
        for (int it = 0; it < 4; it++) {
            int idx = tid + it * 128;
            int kq = idx & 7, m = idx >> 3;
            float4 v = *reinterpret_cast<const float4*>(&A[(long)(m0 + m) * lda + k0 + kq * 4]);
            uint4 w;
            split2u(v.x, v.y, w.x, w.y);
            split2u(v.z, v.w, w.z, w.w);
            *reinterpret_cast<uint4*>(&sA[m][2 * kq]) = w;
        }
        // ---- stage B ----
        if (BSP == 1) {
#pragma unroll
            for (int it = 0; it < 4; it++) {
                int idx = tid + it * 128;
                int kq = idx & 7, n = idx >> 3;
                float4 v = *reinterpret_cast<const float4*>(&B[(long)(n0 + n) * ldb + k0 + kq * 4]);
                uint4 w;
                split2u(v.x, v.y, w.x, w.y);
                split2u(v.z, v.w, w.z, w.w);
                *reinterpret_cast<uint4*>(&sB[n][2 * kq]) = w;
            }
        } else {
#pragma unroll
            for (int it = 0; it < 2; it++) {
                int idx = tid + it * 128;
                int c = idx & 3, n = idx >> 2;
                uint4 v = *reinterpret_cast<const uint4*>(&Bb[(long)(n0 + n) * ldb + k0 + c * 8]);
                uint4 w1 = make_uint4(v.x, 0u, v.y, 0u);
                uint4 w2 = make_uint4(v.z, 0u, v.w, 0u);
                *reinterpret_cast<uint4*>(&sB[n][4 * c])     = w1;
                *reinterpret_cast<uint4*>(&sB[n][4 * c + 2]) = w2;
            }
        }
        __syncthreads();

#pragma unroll
        for (int ks = 0; ks < 2; ks++) {
            const int e = ks * 8 + p;
            uint32_t ah[2][4], al[2][4], bh[4][2], bl[4][2];
#pragma unroll
            for (int mt = 0; mt < 2; mt++) {
                int row = m0w + mt * 16 + r;
                uint2 a0 = sA[row][e],     a1 = sA[row + 8][e];
                uint2 a2 = sA[row][e + 4], a3 = sA[row + 8][e + 4];
                ah[mt][0] = a0.x; ah[mt][1] = a1.x; ah[mt][2] = a2.x; ah[mt][3] = a3.x;
                al[mt][0] = a0.y; al[mt][1] = a1.y; al[mt][2] = a2.y; al[mt][3] = a3.y;
            }
#pragma unroll
            for (int nt = 0; nt < 4; nt++) {
                int nrow = n0w + nt * 8 + r;
                uint2 b0 = sB[nrow][e], b1 = sB[nrow][e + 4];
                bh[nt][0] = b0.x; bh[nt][1] = b1.x;
                if (BSP == 1) { bl[nt][0] = b0.y; bl[nt][1] = b1.y; }
            }
#pragma unroll
            for (int mt = 0; mt < 2; mt++)
#pragma unroll
                for (int nt = 0; nt < 4; nt++) {
                    mma_bf16(acc[mt][nt], ah[mt], bh[nt]);      // hi*hi
                    if (BSP == 1) mma_bf16(acc[mt][nt], ah[mt], bl[nt]);  // hi*lo
                    mma_bf16(acc[mt][nt], al[mt], bh[nt]);      // lo*hi
                }
        }
        __syncthreads();
    }

    // ---- epilogue ----
    float sum = 0.f, ss = 0.f;
#pragma unroll
    for (int mt = 0; mt < 2; mt++) {
        int row = m0 + m0w + mt * 16 + r;
#pragma unroll
        for (int nt = 0; nt < 4; nt++) {
            int col = n0 + n0w + nt * 8 + 2 * p;
            float x0 = alpha * acc[mt][nt][0], y0 = alpha * acc[mt][nt][1];
            float x1 = alpha * acc[mt][nt][2], y1 = alpha * acc[mt][nt][3];
            *reinterpret_cast<float2*>(&C[(long)row * ldc + col])       = make_float2(x0, y0);
            *reinterpret_cast<float2*>(&C[(long)(row + 8) * ldc + col]) = make_float2(x1, y1);
            if (MODE == 2) {
                sum += x0 + y0 + x1 + y1;
                ss  += x0*x0 + y0*y0 + x1*x1 + y1*y1;
            }
        }
    }
    if (MODE == 2) {
#pragma unroll
        for (int o = 16; o; o >>= 1) {
            sum += __shfl_xor_sync(0xffffffffu, sum, o);
            ss  += __shfl_xor_sync(0xffffffffu, ss, o);
        }
        __shared__ float red[8];
        if (lane == 0) { red[warp] = sum; red[4 + warp] = ss; }
        __syncthreads();
        if (tid == 0) {
            float s1 = red[0] + red[1] + red[2] + red[3];
            float s2 = red[4] + red[5] + red[6] + red[7];
            int g  = br * 64 + z;
            int bz = tl * gridDim.x + blockIdx.x;
            part[((long)g * 128 + bz) * 2 + 0] = s1;
            part[((long)g * 128 + bz) * 2 + 1] = s2;
        }
    }
}

// ================= stats finalize: 256 groups, deterministic =================
__global__ void stats_fin(const float* __restrict__ part, float* __restrict__ stats)
{
    const int g = blockIdx.x;
    const int br = g >> 6;
    const int nbTab[4]  = {15, 30, 60, 120};
    const float ivTab[4] = {1.f/(64*960.f), 1.f/(128*960.f), 1.f/(256*960.f), 1.f/(512*960.f)};
    const int nb = nbTab[br];
    const int tid = threadIdx.x;
    __shared__ float s1[128], s2[128];
    float a = 0.f, b = 0.f;
    for (int i = tid; i < nb; i += 128) {
        a += part[((long)g * 128 + i) * 2 + 0];
        b += part[((long)g * 128 + i) * 2 + 1];
    }
    s1[tid] = a; s2[tid] = b; __syncthreads();
    for (int o = 64; o; o >>= 1) {
        if (tid < o) { s1[tid] += s1[tid + o]; s2[tid] += s2[tid + o]; }
        __syncthreads();
    }
    if (tid == 0) {
        float m = s1[0] * ivTab[br];
        float v = s2[0] * ivTab[br] - m * m;
        stats[2 * g]     = m;
        stats[2 * g + 1] = rsqrtf(v + 1e-5f);
    }
}

// ======== warp-per-row inorm apply + softmax over 960, bf16 out ==============
__global__ void inorm_softmax_warp(const float* __restrict__ S, const float* __restrict__ stats,
                                   __nv_bfloat16* __restrict__ P)
{
    const int warp = threadIdx.x >> 5, lane = threadIdx.x & 31;
    const int row = blockIdx.x * 8 + warp;           // 61440 rows total
    const int z = row / 960, mr = row - z * 960;
    const int br = (mr < 64) ? 0 : (mr < 192) ? 1 : (mr < 448) ? 2 : 3;
    const int g = br * 64 + z;
    const float* p = S + (long)row * 960;
    __nv_bfloat16* q = P + (long)row * 960;
    const float mean = stats[2 * g], rstd = stats[2 * g + 1];

    float4 v[8];
    float mx = -1e30f;
#pragma unroll
    for (int i = 0; i < 7; i++) {
        float4 t = *reinterpret_cast<const float4*>(&p[(lane + 32 * i) * 4]);
        t.x = (t.x - mean) * rstd; t.y = (t.y - mean) * rstd;
        t.z = (t.z - mean) * rstd; t.w = (t.w - mean) * rstd;
        v[i] = t;
        mx = fmaxf(mx, fmaxf(fmaxf(t.x, t.y), fmaxf(t.z, t.w)));
    }
    if (lane < 16) {
        float4 t = *reinterpret_cast<const float4*>(&p[(224 + lane) * 4]);
        t.x = (t.x - mean) * rstd; t.y = (t.y - mean) * rstd;
        t.z = (t.z - mean) * rstd; t.w = (t.w - mean) * rstd;
        v[7] = t;
        mx = fmaxf(mx, fmaxf(fmaxf(t.x, t.y), fmaxf(t.z, t.w)));
    }
#pragma unroll
    for (int o = 16; o; o >>= 1) mx = fmaxf(mx, __shfl_xor_sync(0xffffffffu, mx, o));

    float sum = 0.f;
#pragma unroll
    for (int i = 0; i < 7; i++) {
        v[i].x = __expf(v[i].x - mx); v[i].y = __expf(v[i].y - mx);
        v[i].z = __expf(v[i].z - mx); v[i].w = __expf(v[i].w - mx);
        sum += v[i].x + v[i].y + v[i].z + v[i].w;
    }
    if (lane < 16) {
        v[7].x = __expf(v[7].x - mx); v[7].y = __expf(v[7].y - mx);
        v[7].z = __expf(v[7].z - mx); v[7].w = __expf(v[7].w - mx);
        sum += v[7].x + v[7].y + v[7].z + v[7].w;
    }
#pragma unroll
    for (int o = 16; o; o >>= 1) sum += __shfl_xor_sync(0xffffffffu, sum, o);
    const float inv = 1.f / sum;

#pragma unroll
    for (int i = 0; i < 7; i++) {
        __nv_bfloat162 h0, h1;
        h0.x = __float2bfloat16(v[i].x * inv); h0.y = __float2bfloat16(v[i].y * inv);
        h1.x = __float2bfloat16(v[i].z * inv); h1.y = __float2bfloat16(v[i].w * inv);
        uint2 w;
        w.x = *reinterpret_cast<uint32_t*>(&h0);
        w.y = *reinterpret_cast<uint32_t*>(&h1);
        *reinterpret_cast<uint2*>(&q[(lane + 32 * i) * 4]) = w;
    }
    if (lane < 16) {
        __nv_bfloat162 h0, h1;
        h0.x = __float2bfloat16(v[7].x * inv); h0.y = __float2bfloat16(v[7].y * inv);
        h1.x = __float2bfloat16(v[7].z * inv); h1.y = __float2bfloat16(v[7].w * inv);
        uint2 w;
        w.x = *reinterpret_cast<uint32_t*>(&h0);
        w.y = *reinterpret_cast<uint32_t*>(&h1);
        *reinterpret_cast<uint2*>(&q[(224 + lane) * 4]) = w;
    }
}

// ================= transpose: [z][128][960] -> [z][960][128], fp32 ===========
__global__ void transpose_kvt(const float* __restrict__ in, float* __restrict__ out)
{
    __shared__ float t[32][33];
    const int b = blockIdx.z;
    const int s0 = blockIdx.x * 32, n0 = blockIdx.y * 32;
    in  += (long)b * 128 * 960;
    out += (long)b * 960 * 128;
    const int tx = threadIdx.x, ty = threadIdx.y;
#pragma unroll
    for (int i = 0; i < 4; i++)
        t[ty + 8 * i][tx] = in[(long)(n0 + ty + 8 * i) * 960 + s0 + tx];
    __syncthreads();
#pragma unroll
    for (int i = 0; i < 4; i++)
        out[(long)(s0 + ty + 8 * i) * 128 + n0 + tx] = t[tx][ty + 8 * i];
}

// ================= host side =================
extern "C" void kernel_launch(void* const* d_in, const int* in_sizes, int n_in,
                              void* d_out, int out_size)
{
    const float* Q[4]  = {(const float*)d_in[0], (const float*)d_in[1],
                          (const float*)d_in[2], (const float*)d_in[3]};
    const float* KV    = (const float*)d_in[4];
    const float* Wk    = (const float*)d_in[5];
    const float* Wv    = (const float*)d_in[6];
    const float* Wq[4] = {(const float*)d_in[7], (const float*)d_in[8],
                          (const float*)d_in[9], (const float*)d_in[10]};
    const float* Wo[4] = {(const float*)d_in[11], (const float*)d_in[12],
                          (const float*)d_in[13], (const float*)d_in[14]};
    float* out = (float*)d_out;

    float *Kt, *KVt, *QtT, *S, *O, *part, *stats;
    __nv_bfloat16* P;
    cudaGetSymbolAddress((void**)&Kt,   g_Kt);
    cudaGetSymbolAddress((void**)&KVt,  g_KVt);
    cudaGetSymbolAddress((void**)&QtT,  g_QtT);
    cudaGetSymbolAddress((void**)&S,    g_S);
    cudaGetSymbolAddress((void**)&P,    g_P);
    cudaGetSymbolAddress((void**)&O,    g_O);
    cudaGetSymbolAddress((void**)&part, g_part);
    cudaGetSymbolAddress((void**)&stats,g_stats);

    const int FULL = 0x7FFFFFFF;
    const float inv_scale = 1.0f / sqrtf(960.0f);
    const int Cq[4]   = {64, 128, 256, 512};
    const int moff[4] = {0, 64, 192, 448};   // concat row offsets (sum = 960)

    GP gp;

    // ---- 1) Kt = KV @ Wk^T ----
    for (int i = 0; i < 4; i++) {
        gp.A[i] = KV;  gp.B[i] = Wk;  gp.C[i] = Kt;
        gp.K[i] = 960; gp.lda[i] = 960; gp.ldb[i] = 960; gp.ldc[i] = 960;
        gp.aMask[i] = FULL; gp.bMask[i] = 7;
        gp.aS[i] = 128L*960; gp.bS[i] = 960L*960; gp.cS[i] = 128L*960;
        gp.alpha[i] = 1.f;
    }
    gp.cum0 = 1000; gp.cum1 = 1001; gp.cum2 = 1002;
    gemm_mg<0,0,1><<<dim3(15, 2, 64), 128>>>(gp, part);

    // ---- 2) KVt = Kt @ Wv^T ----
    for (int i = 0; i < 4; i++) { gp.A[i] = Kt; gp.B[i] = Wv; gp.C[i] = KVt; }
    gemm_mg<0,0,1><<<dim3(15, 2, 64), 128>>>(gp, part);

    // ---- 3) KVtT [z][960][128] (reuse Kt) ----
    float* KVtT = Kt;
    transpose_kvt<<<dim3(30, 4, 64), dim3(32, 8)>>>(KVt, KVtT);

    // ---- 4) QtT merged: QtT[c,n] = sum_k Wq[c,k] * Q[n,k]  (M=Cq merged on y) ----
    for (int i = 0; i < 4; i++) {
        gp.A[i] = Wq[i];          gp.B[i] = Q[i];           gp.C[i] = QtT + (long)moff[i] * 128;
        gp.K[i] = Cq[i];          gp.lda[i] = Cq[i];        gp.ldb[i] = Cq[i];  gp.ldc[i] = 128;
        gp.aMask[i] = 7;          gp.bMask[i] = FULL;
        gp.aS[i] = (long)Cq[i]*Cq[i]; gp.bS[i] = 128L*Cq[i]; gp.cS[i] = 960L*128;
        gp.alpha[i] = 1.f;
    }
    gp.cum0 = 1; gp.cum1 = 3; gp.cum2 = 7;   // m-tiles {1,2,4,8}
    gemm_mg<0,0,1><<<dim3(2, 15, 64), 128>>>(gp, part);

    // ---- 5) S merged: S[c,s] = inv_scale * sum_n QtT[c,n]*KVtT[s,n] (+ stats partials) ----
    for (int i = 0; i < 4; i++) {
        gp.A[i] = QtT + (long)moff[i] * 128;  gp.B[i] = KVtT;  gp.C[i] = S + (long)moff[i] * 960;
        gp.K[i] = 128;  gp.lda[i] = 128; gp.ldb[i] = 128; gp.ldc[i] = 960;
        gp.aMask[i] = FULL; gp.bMask[i] = FULL;
        gp.aS[i] = 960L*128; gp.bS[i] = 960L*128; gp.cS[i] = 960L*960;
        gp.alpha[i] = inv_scale;
    }
    gp.cum0 = 1; gp.cum1 = 3; gp.cum2 = 7;
    gemm_mg<0,2,1><<<dim3(15, 15, 64), 128>>>(gp, part);

    // ---- 6) stats + 7) softmax (warp-per-row, bf16 P out) ----
    stats_fin<<<256, 128>>>(part, stats);
    inorm_softmax_warp<<<7680, 256>>>(S, stats, P);

    // ---- 8) O merged: O[n,c] = sum_s KVt[n,s]*P[c,s]  (N=Cq merged on x, B=bf16) ----
    for (int i = 0; i < 4; i++) {
        gp.A[i] = KVt;
        gp.B[i] = reinterpret_cast<const float*>(P + (long)moff[i] * 960);
        gp.C[i] = O + moff[i];
        gp.K[i] = 960;  gp.lda[i] = 960; gp.ldb[i] = 960;   gp.ldc[i] = 960;
        gp.aMask[i] = FULL; gp.bMask[i] = FULL;
        gp.aS[i] = 128L*960; gp.bS[i] = 960L*960; gp.cS[i] = 128L*960;   // bS in bf16 elems
        gp.alpha[i] = 1.f;
    }
    gp.cum0 = 1; gp.cum1 = 3; gp.cum2 = 7;   // n-tiles {1,2,4,8}
    gemm_mg<1,0,0><<<dim3(15, 2, 64), 128>>>(gp, part);

    // ---- 9) Wo merged: Y = O @ Wo^T  (N=Cq merged on x, M=8192) ----
    for (int i = 0; i < 4; i++) {
        gp.A[i] = O + moff[i];  gp.B[i] = Wo[i];  gp.C[i] = out + 8192L * moff[i];
        gp.K[i] = Cq[i];  gp.lda[i] = 960; gp.ldb[i] = Cq[i]; gp.ldc[i] = Cq[i];
        gp.aMask[i] = 0; gp.bMask[i] = 0;
        gp.aS[i] = 0; gp.bS[i] = 0; gp.cS[i] = 0;
        gp.alpha[i] = 1.f;
    }
    gp.cum0 = 1; gp.cum1 = 3; gp.cum2 = 7;
    gemm_mg<1,0,1><<<dim3(15, 128, 1), 128>>>(gp, part);
}

// round 14
// speedup vs baseline: 1.3561x; 1.0432x over previous
#include <cuda_runtime.h>
#include <cuda_fp16.h>
#include <math.h>
#include <stdint.h>

// ================= scratch (device globals: allocation-free) =================
// interleaved format: uint2 {fp16 hi-pair (k,k+1), fp16 lo-pair (k,k+1)}
__device__ uint2  g_Kti  [3932160];   // Kt   [64][128][480 pairs]
__device__ uint2  g_KVti [3932160];   // KVt  [64][128][480 pairs]
__device__ uint2  g_KVtTi[3932160];   // KVtT [64][960][64 pairs]
__device__ uint2  g_QtTi [3932160];   // QtT  [64][960 concat][64 pairs]
__device__ uint2  g_Oi   [3932160];   // O    [8192][480 pairs]
__device__ __half g_P    [58982400];  // P    [64][960 concat][960] fp16
__device__ float  g_S    [58982400];  // S    [64][960 concat][960] fp32
__device__ float  g_part [65536];
__device__ float  g_stats[512];

// ================= per-branch GEMM params =================
struct GP {
    const float* A[4]; const float* B[4]; float* C[4];
    int  K[4], lda[4], ldb[4], ldc[4], aMask[4], bMask[4];
    long aS[4], bS[4], cS[4];
    float alpha[4];
    int cum0, cum1, cum2;
};

// ================= helpers =================
__device__ __forceinline__ void mma_f16(float* c, const uint32_t* a, const uint32_t* b)
{
    asm volatile(
        "mma.sync.aligned.m16n8k16.row.col.f32.f16.f16.f32 "
        "{%0,%1,%2,%3}, {%4,%5,%6,%7}, {%8,%9}, {%0,%1,%2,%3};"
        : "+f"(c[0]), "+f"(c[1]), "+f"(c[2]), "+f"(c[3])
        : "r"(a[0]), "r"(a[1]), "r"(a[2]), "r"(a[3]), "r"(b[0]), "r"(b[1]));
}

__device__ __forceinline__ void splith(float x, float y, uint32_t& h, uint32_t& l)
{
    __half hx = __float2half_rn(x), hy = __float2half_rn(y);
    __half lx = __float2half_rn(x - __half2float(hx));
    __half ly = __float2half_rn(y - __half2float(hy));
    __half2 hh = __halves2half2(hx, hy), ll = __halves2half2(lx, ly);
    h = *reinterpret_cast<uint32_t*>(&hh);
    l = *reinterpret_cast<uint32_t*>(&ll);
}

// ================= merged NT GEMM, fp16 hi/lo-interleaved smem ===============
// C[m,n] = alpha * sum_k A[m,k]*B[n,k].  BM=BN=64, BK=32, 128 threads.
// AXIS: 0 = branch from blockIdx.y (M merged), 1 = from blockIdx.x (N merged).
// MODE: 0 fp32 C; 1 interleaved uint2 C; 2 fp32 C + per-block stats partials.
// ASRC: 0 = fp32 (split at stage), 1 = interleaved uint2 (copy stage).
// BSRC: 0 = fp32 split, 1 = interleaved copy, 2 = fp16 single (2 products).
template<int AXIS, int MODE, int ASRC, int BSRC>
__global__ void __launch_bounds__(128)
gemm_mg(GP gp, float* __restrict__ part)
{
    constexpr int LDE = 20;                       // uint2 per row (160B stride)
    __shared__ uint2 sA[64][LDE];
    __shared__ uint2 sB[64][LDE];

    const int t = (AXIS == 0) ? blockIdx.y : blockIdx.x;
    int br, tl;
    if      (t < gp.cum0) { br = 0; tl = t; }
    else if (t < gp.cum1) { br = 1; tl = t - gp.cum0; }
    else if (t < gp.cum2) { br = 2; tl = t - gp.cum1; }
    else                  { br = 3; tl = t - gp.cum2; }

    const float *Ap, *Bp; float* Cp;
    int K, lda, ldb, ldc, aM, bM; long aS, bS, cS; float alpha;
#define PICK(i) { Ap=gp.A[i]; Bp=gp.B[i]; Cp=gp.C[i]; K=gp.K[i]; lda=gp.lda[i]; ldb=gp.ldb[i]; \
                  ldc=gp.ldc[i]; aM=gp.aMask[i]; bM=gp.bMask[i]; aS=gp.aS[i]; bS=gp.bS[i]; \
                  cS=gp.cS[i]; alpha=gp.alpha[i]; }
    switch (br) { case 0: PICK(0); break; case 1: PICK(1); break;
                  case 2: PICK(2); break; default: PICK(3); break; }
#undef PICK

    const int z = blockIdx.z;
    const float* Af = nullptr; const uint2* Ai = nullptr;
    if (ASRC == 0) Af = Ap + (long)(z & aM) * aS;
    else           Ai = reinterpret_cast<const uint2*>(Ap) + (long)(z & aM) * aS;
    const float* Bf = nullptr; const uint2* Bi = nullptr; const __half* Bh2 = nullptr;
    if      (BSRC == 0) Bf  = Bp + (long)(z & bM) * bS;
    else if (BSRC == 1) Bi  = reinterpret_cast<const uint2*>(Bp) + (long)(z & bM) * bS;
    else                Bh2 = reinterpret_cast<const __half*>(Bp) + (long)(z & bM) * bS;
    float* Cf = nullptr; uint2* Ci = nullptr;
    if (MODE == 1) Ci = reinterpret_cast<uint2*>(Cp) + (long)z * cS;
    else           Cf = Cp + (long)z * cS;

    const int m0 = (AXIS == 0 ? tl : (int)blockIdx.y) * 64;
    const int n0 = (AXIS == 0 ? (int)blockIdx.x : tl) * 64;
    const int tid = threadIdx.x, lane = tid & 31, warp = tid >> 5;
    const int wy = warp >> 1, wx = warp & 1;
    const int m0w = wy * 32, n0w = wx * 32;
    const int r = lane >> 2, p = lane & 3;

    float acc[2][4][4];
#pragma unroll
    for (int mt = 0; mt < 2; mt++)
#pragma unroll
        for (int nt = 0; nt < 4; nt++)
#pragma unroll
            for (int i = 0; i < 4; i++) acc[mt][nt][i] = 0.f;

    for (int k0 = 0; k0 < K; k0 += 32) {
        // ---- stage A ----
        if (ASRC == 0) {
#pragma unroll
            for (int it = 0; it < 4; it++) {
                int idx = tid + it * 128;
                int kq = idx & 7, m = idx >> 3;
                float4 v = *reinterpret_cast<const float4*>(&Af[(long)(m0 + m) * lda + k0 + kq * 4]);
                uint4 w;
                splith(v.x, v.y, w.x, w.y);
                splith(v.z, v.w, w.z, w.w);
                *reinterpret_cast<uint4*>(&sA[m][2 * kq]) = w;
            }
        } else {
#pragma unroll
            for (int it = 0; it < 4; it++) {
                int idx = tid + it * 128;
                int c = idx & 7, m = idx >> 3;
                uint4 v = *reinterpret_cast<const uint4*>(&Ai[(long)(m0 + m) * lda + (k0 >> 1) + c * 2]);
                *reinterpret_cast<uint4*>(&sA[m][c * 2]) = v;
            }
        }
        // ---- stage B ----
        if (BSRC == 0) {
#pragma unroll
            for (int it = 0; it < 4; it++) {
                int idx = tid + it * 128;
                int kq = idx & 7, n = idx >> 3;
                float4 v = *reinterpret_cast<const float4*>(&Bf[(long)(n0 + n) * ldb + k0 + kq * 4]);
                uint4 w;
                splith(v.x, v.y, w.x, w.y);
                splith(v.z, v.w, w.z, w.w);
                *reinterpret_cast<uint4*>(&sB[n][2 * kq]) = w;
            }
        } else if (BSRC == 1) {
#pragma unroll
            for (int it = 0; it < 4; it++) {
                int idx = tid + it * 128;
                int c = idx & 7, n = idx >> 3;
                uint4 v = *reinterpret_cast<const uint4*>(&Bi[(long)(n0 + n) * ldb + (k0 >> 1) + c * 2]);
                *reinterpret_cast<uint4*>(&sB[n][c * 2]) = v;
            }
        } else {
#pragma unroll
            for (int it = 0; it < 2; it++) {
                int idx = tid + it * 128;
                int c = idx & 3, n = idx >> 2;
                uint4 v = *reinterpret_cast<const uint4*>(&Bh2[(long)(n0 + n) * ldb + k0 + c * 8]);
                sB[n][c * 4 + 0].x = v.x;
                sB[n][c * 4 + 1].x = v.y;
                sB[n][c * 4 + 2].x = v.z;
                sB[n][c * 4 + 3].x = v.w;
            }
        }
        __syncthreads();

#pragma unroll
        for (int ks = 0; ks < 2; ks++) {
            const int e = ks * 8 + p;
            uint32_t ah[2][4], al[2][4], bh[4][2], bl[4][2];
#pragma unroll
            for (int mt = 0; mt < 2; mt++) {
                int row = m0w + mt * 16 + r;
                uint2 a0 = sA[row][e],     a1 = sA[row + 8][e];
                uint2 a2 = sA[row][e + 4], a3 = sA[row + 8][e + 4];
                ah[mt][0] = a0.x; ah[mt][1] = a1.x; ah[mt][2] = a2.x; ah[mt][3] = a3.x;
                al[mt][0] = a0.y; al[mt][1] = a1.y; al[mt][2] = a2.y; al[mt][3] = a3.y;
            }
#pragma unroll
            for (int nt = 0; nt < 4; nt++) {
                int nrow = n0w + nt * 8 + r;
                uint2 b0 = sB[nrow][e], b1 = sB[nrow][e + 4];
                bh[nt][0] = b0.x; bh[nt][1] = b1.x;
                if (BSRC != 2) { bl[nt][0] = b0.y; bl[nt][1] = b1.y; }
            }
#pragma unroll
            for (int mt = 0; mt < 2; mt++)
#pragma unroll
                for (int nt = 0; nt < 4; nt++) {
                    mma_f16(acc[mt][nt], ah[mt], bh[nt]);                 // hi*hi
                    if (BSRC != 2) mma_f16(acc[mt][nt], ah[mt], bl[nt]);  // hi*lo
                    mma_f16(acc[mt][nt], al[mt], bh[nt]);                 // lo*hi
                }
        }
        __syncthreads();
    }

    // ---- epilogue ----
    float sum = 0.f, ss = 0.f;
#pragma unroll
    for (int mt = 0; mt < 2; mt++) {
        int row = m0 + m0w + mt * 16 + r;
#pragma unroll
        for (int nt = 0; nt < 4; nt++) {
            int col = n0 + n0w + nt * 8 + 2 * p;
            float x0 = alpha * acc[mt][nt][0], y0 = alpha * acc[mt][nt][1];
            float x1 = alpha * acc[mt][nt][2], y1 = alpha * acc[mt][nt][3];
            if (MODE == 1) {
                uint32_t h, l;
                splith(x0, y0, h, l);
                Ci[(long)row * ldc + (col >> 1)] = make_uint2(h, l);
                splith(x1, y1, h, l);
                Ci[(long)(row + 8) * ldc + (col >> 1)] = make_uint2(h, l);
            } else {
                *reinterpret_cast<float2*>(&Cf[(long)row * ldc + col])       = make_float2(x0, y0);
                *reinterpret_cast<float2*>(&Cf[(long)(row + 8) * ldc + col]) = make_float2(x1, y1);
                if (MODE == 2) {
                    sum += x0 + y0 + x1 + y1;
                    ss  += x0*x0 + y0*y0 + x1*x1 + y1*y1;
                }
            }
        }
    }
    if (MODE == 2) {
#pragma unroll
        for (int o = 16; o; o >>= 1) {
            sum += __shfl_xor_sync(0xffffffffu, sum, o);
            ss  += __shfl_xor_sync(0xffffffffu, ss, o);
        }
        __shared__ float red[8];
        if (lane == 0) { red[warp] = sum; red[4 + warp] = ss; }
        __syncthreads();
        if (tid == 0) {
            float s1 = red[0] + red[1] + red[2] + red[3];
            float s2 = red[4] + red[5] + red[6] + red[7];
            int g  = br * 64 + z;
            int bz = tl * gridDim.x + blockIdx.x;
            part[((long)g * 128 + bz) * 2 + 0] = s1;
            part[((long)g * 128 + bz) * 2 + 1] = s2;
        }
    }
}

// ================= stats finalize: 256 groups, deterministic =================
__global__ void stats_fin(const float* __restrict__ part, float* __restrict__ stats)
{
    const int g = blockIdx.x;
    const int br = g >> 6;
    const int nbTab[4]  = {15, 30, 60, 120};
    const float ivTab[4] = {1.f/(64*960.f), 1.f/(128*960.f), 1.f/(256*960.f), 1.f/(512*960.f)};
    const int nb = nbTab[br];
    const int tid = threadIdx.x;
    __shared__ float s1[128], s2[128];
    float a = 0.f, b = 0.f;
    for (int i = tid; i < nb; i += 128) {
        a += part[((long)g * 128 + i) * 2 + 0];
        b += part[((long)g * 128 + i) * 2 + 1];
    }
    s1[tid] = a; s2[tid] = b; __syncthreads();
    for (int o = 64; o; o >>= 1) {
        if (tid < o) { s1[tid] += s1[tid + o]; s2[tid] += s2[tid + o]; }
        __syncthreads();
    }
    if (tid == 0) {
        float m = s1[0] * ivTab[br];
        float v = s2[0] * ivTab[br] - m * m;
        stats[2 * g]     = m;
        stats[2 * g + 1] = rsqrtf(v + 1e-5f);
    }
}

// ======== warp-per-row inorm apply + softmax over 960, fp16 out ==============
__global__ void inorm_softmax_warp(const float* __restrict__ S, const float* __restrict__ stats,
                                   __half* __restrict__ P)
{
    const int warp = threadIdx.x >> 5, lane = threadIdx.x & 31;
    const int row = blockIdx.x * 8 + warp;
    const int z = row / 960, mr = row - z * 960;
    const int br = (mr < 64) ? 0 : (mr < 192) ? 1 : (mr < 448) ? 2 : 3;
    const int g = br * 64 + z;
    const float* p = S + (long)row * 960;
    __half* q = P + (long)row * 960;
    const float mean = stats[2 * g], rstd = stats[2 * g + 1];

    float4 v[8];
    float mx = -1e30f;
#pragma unroll
    for (int i = 0; i < 7; i++) {
        float4 tv = *reinterpret_cast<const float4*>(&p[(lane + 32 * i) * 4]);
        tv.x = (tv.x - mean) * rstd; tv.y = (tv.y - mean) * rstd;
        tv.z = (tv.z - mean) * rstd; tv.w = (tv.w - mean) * rstd;
        v[i] = tv;
        mx = fmaxf(mx, fmaxf(fmaxf(tv.x, tv.y), fmaxf(tv.z, tv.w)));
    }
    if (lane < 16) {
        float4 tv = *reinterpret_cast<const float4*>(&p[(224 + lane) * 4]);
        tv.x = (tv.x - mean) * rstd; tv.y = (tv.y - mean) * rstd;
        tv.z = (tv.z - mean) * rstd; tv.w = (tv.w - mean) * rstd;
        v[7] = tv;
        mx = fmaxf(mx, fmaxf(fmaxf(tv.x, tv.y), fmaxf(tv.z, tv.w)));
    }
#pragma unroll
    for (int o = 16; o; o >>= 1) mx = fmaxf(mx, __shfl_xor_sync(0xffffffffu, mx, o));

    float sum = 0.f;
#pragma unroll
    for (int i = 0; i < 7; i++) {
        v[i].x = __expf(v[i].x - mx); v[i].y = __expf(v[i].y - mx);
        v[i].z = __expf(v[i].z - mx); v[i].w = __expf(v[i].w - mx);
        sum += v[i].x + v[i].y + v[i].z + v[i].w;
    }
    if (lane < 16) {
        v[7].x = __expf(v[7].x - mx); v[7].y = __expf(v[7].y - mx);
        v[7].z = __expf(v[7].z - mx); v[7].w = __expf(v[7].w - mx);
        sum += v[7].x + v[7].y + v[7].z + v[7].w;
    }
#pragma unroll
    for (int o = 16; o; o >>= 1) sum += __shfl_xor_sync(0xffffffffu, sum, o);
    const float inv = 1.f / sum;

#pragma unroll
    for (int i = 0; i < 7; i++) {
        __half2 a = __halves2half2(__float2half_rn(v[i].x * inv), __float2half_rn(v[i].y * inv));
        __half2 b = __halves2half2(__float2half_rn(v[i].z * inv), __float2half_rn(v[i].w * inv));
        uint2 w;
        w.x = *reinterpret_cast<uint32_t*>(&a);
        w.y = *reinterpret_cast<uint32_t*>(&b);
        *reinterpret_cast<uint2*>(&q[(lane + 32 * i) * 4]) = w;
    }
    if (lane < 16) {
        __half2 a = __halves2half2(__float2half_rn(v[7].x * inv), __float2half_rn(v[7].y * inv));
        __half2 b = __halves2half2(__float2half_rn(v[7].z * inv), __float2half_rn(v[7].w * inv));
        uint2 w;
        w.x = *reinterpret_cast<uint32_t*>(&a);
        w.y = *reinterpret_cast<uint32_t*>(&b);
        *reinterpret_cast<uint2*>(&q[(224 + lane) * 4]) = w;
    }
}

// ====== transpose interleaved: [z][128][480 s-pairs] -> [z][960][64 n-pairs] ==
__global__ void transpose_kvt_i(const uint2* __restrict__ in, uint2* __restrict__ out)
{
    __shared__ float t[32][33];                  // [s local][n local]
    const int z = blockIdx.z;
    const int s0 = blockIdx.x * 32, n0 = blockIdx.y * 32;
    const uint2* ip = in + (long)z * 128 * 480;
    uint2* op = out + (long)z * 960 * 64;
    const int tx = threadIdx.x, ty = threadIdx.y;    // 16x16
#pragma unroll
    for (int i = 0; i < 2; i++) {
        int n = n0 + ty + 16 * i;
        uint2 e = ip[(long)n * 480 + (s0 >> 1) + tx];
        __half2 hh = *reinterpret_cast<__half2*>(&e.x);
        __half2 ll = *reinterpret_cast<__half2*>(&e.y);
        t[2 * tx    ][ty + 16 * i] = __half2float(hh.x) + __half2float(ll.x);
        t[2 * tx + 1][ty + 16 * i] = __half2float(hh.y) + __half2float(ll.y);
    }
    __syncthreads();
#pragma unroll
    for (int i = 0; i < 2; i++) {
        int s = s0 + ty + 16 * i;
        float a = t[ty + 16 * i][2 * tx], b = t[ty + 16 * i][2 * tx + 1];
        uint32_t h, l;
        splith(a, b, h, l);
        op[(long)s * 64 + (n0 >> 1) + tx] = make_uint2(h, l);
    }
}

// ================= host side =================
extern "C" void kernel_launch(void* const* d_in, const int* in_sizes, int n_in,
                              void* d_out, int out_size)
{
    const float* Q[4]  = {(const float*)d_in[0], (const float*)d_in[1],
                          (const float*)d_in[2], (const float*)d_in[3]};
    const float* KV    = (const float*)d_in[4];
    const float* Wk    = (const float*)d_in[5];
    const float* Wv    = (const float*)d_in[6];
    const float* Wq[4] = {(const float*)d_in[7], (const float*)d_in[8],
                          (const float*)d_in[9], (const float*)d_in[10]};
    const float* Wo[4] = {(const float*)d_in[11], (const float*)d_in[12],
                          (const float*)d_in[13], (const float*)d_in[14]};
    float* out = (float*)d_out;

    uint2 *Kti, *KVti, *KVtTi, *QtTi, *Oi;
    __half* P;
    float *S, *part, *stats;
    cudaGetSymbolAddress((void**)&Kti,   g_Kti);
    cudaGetSymbolAddress((void**)&KVti,  g_KVti);
    cudaGetSymbolAddress((void**)&KVtTi, g_KVtTi);
    cudaGetSymbolAddress((void**)&QtTi,  g_QtTi);
    cudaGetSymbolAddress((void**)&Oi,    g_Oi);
    cudaGetSymbolAddress((void**)&P,     g_P);
    cudaGetSymbolAddress((void**)&S,     g_S);
    cudaGetSymbolAddress((void**)&part,  g_part);
    cudaGetSymbolAddress((void**)&stats, g_stats);

    const int FULL = 0x7FFFFFFF;
    const float inv_scale = 1.0f / sqrtf(960.0f);
    const int Cq[4]   = {64, 128, 256, 512};
    const int moff[4] = {0, 64, 192, 448};

    GP gp;

    // ---- 1) Kt = KV @ Wk^T  (fp32 in, interleaved out) ----
    for (int i = 0; i < 4; i++) {
        gp.A[i] = KV;  gp.B[i] = Wk;  gp.C[i] = (float*)Kti;
        gp.K[i] = 960; gp.lda[i] = 960; gp.ldb[i] = 960; gp.ldc[i] = 480;
        gp.aMask[i] = FULL; gp.bMask[i] = 7;
        gp.aS[i] = 128L*960; gp.bS[i] = 960L*960; gp.cS[i] = 128L*480;
        gp.alpha[i] = 1.f;
    }
    gp.cum0 = 1000; gp.cum1 = 1001; gp.cum2 = 1002;
    gemm_mg<0,1,0,0><<<dim3(15, 2, 64), 128>>>(gp, part);

    // ---- 2) KVt = Kt @ Wv^T  (interleaved A copy-stage, interleaved out) ----
    for (int i = 0; i < 4; i++) {
        gp.A[i] = (const float*)Kti; gp.B[i] = Wv; gp.C[i] = (float*)KVti;
        gp.lda[i] = 480; gp.aS[i] = 128L*480;
    }
    gemm_mg<0,1,1,0><<<dim3(15, 2, 64), 128>>>(gp, part);

    // ---- 3) KVtT interleaved transpose ----
    transpose_kvt_i<<<dim3(30, 4, 64), dim3(16, 16)>>>(KVti, KVtTi);

    // ---- 4) QtT merged: QtT[c,n] = sum_k Wq[c,k] * Q[n,k]  (interleaved out) ----
    for (int i = 0; i < 4; i++) {
        gp.A[i] = Wq[i];  gp.B[i] = Q[i];  gp.C[i] = (float*)(QtTi + (long)moff[i] * 64);
        gp.K[i] = Cq[i];  gp.lda[i] = Cq[i]; gp.ldb[i] = Cq[i]; gp.ldc[i] = 64;
        gp.aMask[i] = 7;  gp.bMask[i] = FULL;
        gp.aS[i] = (long)Cq[i]*Cq[i]; gp.bS[i] = 128L*Cq[i]; gp.cS[i] = 960L*64;
        gp.alpha[i] = 1.f;
    }
    gp.cum0 = 1; gp.cum1 = 3; gp.cum2 = 7;
    gemm_mg<0,1,0,0><<<dim3(2, 15, 64), 128>>>(gp, part);

    // ---- 5) S merged: both operands interleaved copy-stage (+ stats) ----
    for (int i = 0; i < 4; i++) {
        gp.A[i] = (const float*)(QtTi + (long)moff[i] * 64);
        gp.B[i] = (const float*)KVtTi;
        gp.C[i] = S + (long)moff[i] * 960;
        gp.K[i] = 128;  gp.lda[i] = 64; gp.ldb[i] = 64; gp.ldc[i] = 960;
        gp.aMask[i] = FULL; gp.bMask[i] = FULL;
        gp.aS[i] = 960L*64; gp.bS[i] = 960L*64; gp.cS[i] = 960L*960;
        gp.alpha[i] = inv_scale;
    }
    gp.cum0 = 1; gp.cum1 = 3; gp.cum2 = 7;
    gemm_mg<0,2,1,1><<<dim3(15, 15, 64), 128>>>(gp, part);

    // ---- 6) stats + 7) softmax (fp16 P out) ----
    stats_fin<<<256, 128>>>(part, stats);
    inorm_softmax_warp<<<7680, 256>>>(S, stats, P);

    // ---- 8) O merged: A=KVt interleaved copy, B=P fp16 (2 products), O interleaved ----
    for (int i = 0; i < 4; i++) {
        gp.A[i] = (const float*)KVti;
        gp.B[i] = (const float*)(P + (long)moff[i] * 960);
        gp.C[i] = (float*)(Oi + moff[i] / 2);
        gp.K[i] = 960;  gp.lda[i] = 480; gp.ldb[i] = 960; gp.ldc[i] = 480;
        gp.aMask[i] = FULL; gp.bMask[i] = FULL;
        gp.aS[i] = 128L*480; gp.bS[i] = 960L*960; gp.cS[i] = 128L*480;
        gp.alpha[i] = 1.f;
    }
    gp.cum0 = 1; gp.cum1 = 3; gp.cum2 = 7;
    gemm_mg<1,1,1,2><<<dim3(15, 2, 64), 128>>>(gp, part);

    // ---- 9) Wo merged: A=O interleaved copy, B=Wo fp32, out fp32 ----
    for (int i = 0; i < 4; i++) {
        gp.A[i] = (const float*)(Oi + moff[i] / 2);
        gp.B[i] = Wo[i];
        gp.C[i] = out + 8192L * moff[i];
        gp.K[i] = Cq[i];  gp.lda[i] = 480; gp.ldb[i] = Cq[i]; gp.ldc[i] = Cq[i];
        gp.aMask[i] = 0; gp.bMask[i] = 0;
        gp.aS[i] = 0; gp.bS[i] = 0; gp.cS[i] = 0;
        gp.alpha[i] = 1.f;
    }
    gp.cum0 = 1; gp.cum1 = 3; gp.cum2 = 7;
    gemm_mg<1,0,1,0><<<dim3(15, 128, 1), 128>>>(gp, part);
}